// round 6
// baseline (speedup 1.0000x reference)
#include <cuda_runtime.h>

#define F_CH   64
#define HW     4096
#define BATCH  32
#define NSTAT  14

__device__ float g_part[F_CH * BATCH * NSTAT];  // per-(f,b) partial stats

struct f8 { float4 a, b; };

// 32-byte (v8.f32) loads with L2 eviction hints. NOT volatile: pure loads,
// let ptxas batch/software-pipeline them.
__device__ __forceinline__ f8 ldg_evl8(const float* p) {  // evict_last: pin in L2
    f8 v;
    asm("ld.global.nc.L2::evict_last.v8.f32 {%0,%1,%2,%3,%4,%5,%6,%7}, [%8];"
        : "=f"(v.a.x), "=f"(v.a.y), "=f"(v.a.z), "=f"(v.a.w),
          "=f"(v.b.x), "=f"(v.b.y), "=f"(v.b.z), "=f"(v.b.w) : "l"(p));
    return v;
}
__device__ __forceinline__ f8 ldg_evf8(const float* p) {  // evict_first: read-once
    f8 v;
    asm("ld.global.nc.L2::evict_first.v8.f32 {%0,%1,%2,%3,%4,%5,%6,%7}, [%8];"
        : "=f"(v.a.x), "=f"(v.a.y), "=f"(v.a.z), "=f"(v.a.w),
          "=f"(v.b.x), "=f"(v.b.y), "=f"(v.b.z), "=f"(v.b.w) : "l"(p));
    return v;
}

__device__ __forceinline__ void acc4(float x0, float x1, float x2, float x3, float* s) {
    s[0] += x0; s[1] += x1; s[2] += x2; s[3] += x3;
    s[4]  = fmaf(x0, x0, s[4]);
    s[5]  = fmaf(x0, x1, s[5]);
    s[6]  = fmaf(x0, x2, s[6]);
    s[7]  = fmaf(x0, x3, s[7]);
    s[8]  = fmaf(x1, x1, s[8]);
    s[9]  = fmaf(x1, x2, s[9]);
    s[10] = fmaf(x1, x3, s[10]);
    s[11] = fmaf(x2, x3, s[11]);
    s[12] = fmaf(x2, x2, s[12]);
    s[13] = fmaf(x3, x3, s[13]);
}
// s layout: 0..3 sums; 4:00 5:01 6:02 7:03 8:11 9:12 10:13 11:23 12:22 13:33

// Pass 1: 512 threads, one 32B chunk per plane per thread (no loop).
// evict_last pins x in L2 for pass2.
__global__ __launch_bounds__(512) void pass1_stats(const float* __restrict__ x) {
    const int f = blockIdx.x;   // 0..63
    const int bb = blockIdx.y;  // 0..31
    const size_t base = ((size_t)bb * 256 + f) * HW;
    const int off = threadIdx.x * 8;   // 512 threads x 8 floats = 4096 = HW

    f8 a = ldg_evl8(x + base + off);
    f8 b = ldg_evl8(x + base + (size_t)64  * HW + off);
    f8 c = ldg_evl8(x + base + (size_t)128 * HW + off);
    f8 d = ldg_evl8(x + base + (size_t)192 * HW + off);

    float s[NSTAT];
#pragma unroll
    for (int k = 0; k < NSTAT; k++) s[k] = 0.f;
    acc4(a.a.x, b.a.x, c.a.x, d.a.x, s);
    acc4(a.a.y, b.a.y, c.a.y, d.a.y, s);
    acc4(a.a.z, b.a.z, c.a.z, d.a.z, s);
    acc4(a.a.w, b.a.w, c.a.w, d.a.w, s);
    acc4(a.b.x, b.b.x, c.b.x, d.b.x, s);
    acc4(a.b.y, b.b.y, c.b.y, d.b.y, s);
    acc4(a.b.z, b.b.z, c.b.z, d.b.z, s);
    acc4(a.b.w, b.b.w, c.b.w, d.b.w, s);

#pragma unroll
    for (int k = 0; k < NSTAT; k++) {
#pragma unroll
        for (int off2 = 16; off2; off2 >>= 1)
            s[k] += __shfl_down_sync(0xffffffffu, s[k], off2);
    }

    __shared__ float sm[16][NSTAT];
    const int warp = threadIdx.x >> 5, lane = threadIdx.x & 31;
    if (lane == 0) {
#pragma unroll
        for (int k = 0; k < NSTAT; k++) sm[warp][k] = s[k];
    }
    __syncthreads();
    if (threadIdx.x < NSTAT) {
        float t = 0.f;
#pragma unroll
        for (int w = 0; w < 16; w++) t += sm[w][threadIdx.x];
        g_part[(f * BATCH + bb) * NSTAT + threadIdx.x] = t;
    }
}

__device__ __forceinline__ float4 mix4(float4 v0, float4 v1, float4 v2, float4 v3,
                                       float w0, float w1, float w2, float w3, float bb) {
    float4 o;
    o.x = fmaf(w0, v0.x, fmaf(w1, v1.x, fmaf(w2, v2.x, fmaf(w3, v3.x, bb))));
    o.y = fmaf(w0, v0.y, fmaf(w1, v1.y, fmaf(w2, v2.y, fmaf(w3, v3.y, bb))));
    o.z = fmaf(w0, v0.z, fmaf(w1, v1.z, fmaf(w2, v2.z, fmaf(w3, v3.z, bb))));
    o.w = fmaf(w0, v0.w, fmaf(w1, v1.w, fmaf(w2, v2.w, fmaf(w3, v3.w, bb))));
    return o;
}

// Pass 2: 512 threads, one chunk per thread. Reverse block order.
// Reads evict_first (single-use), stores st.cs (don't pollute L2).
__global__ __launch_bounds__(512) void pass2_apply(const float* __restrict__ x,
                                                   const float* __restrict__ weight,
                                                   const float* __restrict__ bias,
                                                   float* __restrict__ out) {
    const int rlin = (F_CH * BATCH - 1) - (blockIdx.y * F_CH + blockIdx.x);
    const int f  = rlin % F_CH;
    const int bb = rlin / F_CH;
    __shared__ float AC[20];

    if (threadIdx.x < 32) {
        const int lane = threadIdx.x;
        float s[NSTAT];
#pragma unroll
        for (int k = 0; k < NSTAT; k++) s[k] = g_part[(f * BATCH + lane) * NSTAT + k];
#pragma unroll
        for (int k = 0; k < NSTAT; k++) {
#pragma unroll
            for (int off = 16; off; off >>= 1)
                s[k] += __shfl_down_sync(0xffffffffu, s[k], off);
        }
        if (lane == 0) {
            const float invN = 1.0f / (float)(BATCH * HW);
            const float eps = 1e-5f;
            float m0 = s[0] * invN, m1 = s[1] * invN, m2 = s[2] * invN, m3 = s[3] * invN;
            float c00 = s[4]  * invN - m0 * m0 + eps;
            float c10 = s[5]  * invN - m0 * m1;
            float c20 = s[6]  * invN - m0 * m2;
            float c30 = s[7]  * invN - m0 * m3;
            float c11 = s[8]  * invN - m1 * m1 + eps;
            float c21 = s[9]  * invN - m1 * m2;
            float c31 = s[10] * invN - m1 * m3;
            float c32 = s[11] * invN - m2 * m3;
            float c22 = s[12] * invN - m2 * m2 + eps;
            float c33 = s[13] * invN - m3 * m3 + eps;

            float L00 = sqrtf(c00);
            float L10 = c10 / L00, L20 = c20 / L00, L30 = c30 / L00;
            float L11 = sqrtf(c11 - L10 * L10);
            float L21 = (c21 - L20 * L10) / L11;
            float L31 = (c31 - L30 * L10) / L11;
            float L22 = sqrtf(c22 - L20 * L20 - L21 * L21);
            float L32 = (c32 - L30 * L20 - L31 * L21) / L22;
            float L33 = sqrtf(c33 - L30 * L30 - L31 * L31 - L32 * L32);

            float i00 = 1.f / L00, i11 = 1.f / L11, i22 = 1.f / L22, i33 = 1.f / L33;
            float i10 = -(L10 * i00) * i11;
            float i20 = -(L20 * i00 + L21 * i10) * i22;
            float i21 = -(L21 * i11) * i22;
            float i30 = -(L30 * i00 + L31 * i10 + L32 * i20) * i33;
            float i31 = -(L31 * i11 + L32 * i21) * i33;
            float i32 = -(L32 * i22) * i33;

            float Linv[4][4] = {{i00, 0, 0, 0},
                                {i10, i11, 0, 0},
                                {i20, i21, i22, 0},
                                {i30, i31, i32, i33}};
            float m[4] = {m0, m1, m2, m3};
#pragma unroll
            for (int i = 0; i < 4; i++) {
                float A[4];
#pragma unroll
                for (int j = 0; j < 4; j++) {
                    float t = 0.f;
#pragma unroll
                    for (int k = 0; k < 4; k++)
                        if (k >= j) t = fmaf(weight[(i * 4 + k) * F_CH + f], Linv[k][j], t);
                    A[j] = t;
                    AC[i * 4 + j] = t;
                }
                AC[16 + i] = bias[i * F_CH + f]
                           - (A[0] * m[0] + A[1] * m[1] + A[2] * m[2] + A[3] * m[3]);
            }
        }
    }
    __syncthreads();

    const size_t base = ((size_t)bb * 256 + f) * HW;
    const int off = threadIdx.x * 8;

    f8 v0 = ldg_evf8(x + base + off);
    f8 v1 = ldg_evf8(x + base + (size_t)64  * HW + off);
    f8 v2 = ldg_evf8(x + base + (size_t)128 * HW + off);
    f8 v3 = ldg_evf8(x + base + (size_t)192 * HW + off);

    float a00 = AC[0],  a01 = AC[1],  a02 = AC[2],  a03 = AC[3];
    float a10 = AC[4],  a11 = AC[5],  a12 = AC[6],  a13 = AC[7];
    float a20 = AC[8],  a21 = AC[9],  a22 = AC[10], a23 = AC[11];
    float a30 = AC[12], a31 = AC[13], a32 = AC[14], a33 = AC[15];
    float c0 = AC[16], c1 = AC[17], c2 = AC[18], c3 = AC[19];

    float4* __restrict__ q0 = (float4*)(out + base + off);
    float4* __restrict__ q1 = (float4*)(out + base + (size_t)64  * HW + off);
    float4* __restrict__ q2 = (float4*)(out + base + (size_t)128 * HW + off);
    float4* __restrict__ q3 = (float4*)(out + base + (size_t)192 * HW + off);

    __stcs(q0,     mix4(v0.a, v1.a, v2.a, v3.a, a00, a01, a02, a03, c0));
    __stcs(q0 + 1, mix4(v0.b, v1.b, v2.b, v3.b, a00, a01, a02, a03, c0));
    __stcs(q1,     mix4(v0.a, v1.a, v2.a, v3.a, a10, a11, a12, a13, c1));
    __stcs(q1 + 1, mix4(v0.b, v1.b, v2.b, v3.b, a10, a11, a12, a13, c1));
    __stcs(q2,     mix4(v0.a, v1.a, v2.a, v3.a, a20, a21, a22, a23, c2));
    __stcs(q2 + 1, mix4(v0.b, v1.b, v2.b, v3.b, a20, a21, a22, a23, c2));
    __stcs(q3,     mix4(v0.a, v1.a, v2.a, v3.a, a30, a31, a32, a33, c3));
    __stcs(q3 + 1, mix4(v0.b, v1.b, v2.b, v3.b, a30, a31, a32, a33, c3));
}

extern "C" void kernel_launch(void* const* d_in, const int* in_sizes, int n_in,
                              void* d_out, int out_size) {
    const float* x      = (const float*)d_in[0];
    const float* weight = (const float*)d_in[1];
    const float* bias   = (const float*)d_in[2];
    float* out = (float*)d_out;

    dim3 grid(F_CH, BATCH);
    pass1_stats<<<grid, 512>>>(x);
    pass2_apply<<<grid, 512>>>(x, weight, bias, out);
}

// round 7
// speedup vs baseline: 1.2039x; 1.2039x over previous
#include <cuda_runtime.h>

#define F_CH   64
#define HW     4096
#define BATCH  32
#define NSTAT  14

__device__ float g_part[F_CH * BATCH * NSTAT];  // per-(f,b) partial stats

// createpolicy-based L2 hints on the proven float4 (LDG.E.128) path.
__device__ __forceinline__ unsigned long long pol_evict_last() {
    unsigned long long p;
    asm("createpolicy.fractional.L2::evict_last.b64 %0, 1.0;" : "=l"(p));
    return p;
}
__device__ __forceinline__ unsigned long long pol_evict_first() {
    unsigned long long p;
    asm("createpolicy.fractional.L2::evict_first.b64 %0, 1.0;" : "=l"(p));
    return p;
}
__device__ __forceinline__ float4 ldg_hint(const float4* p, unsigned long long pol) {
    float4 v;
    asm("ld.global.nc.L2::cache_hint.v4.f32 {%0,%1,%2,%3}, [%4], %5;"
        : "=f"(v.x), "=f"(v.y), "=f"(v.z), "=f"(v.w) : "l"(p), "l"(pol));
    return v;
}

__device__ __forceinline__ void acc4(float x0, float x1, float x2, float x3, float* s) {
    s[0] += x0; s[1] += x1; s[2] += x2; s[3] += x3;
    s[4]  = fmaf(x0, x0, s[4]);
    s[5]  = fmaf(x0, x1, s[5]);
    s[6]  = fmaf(x0, x2, s[6]);
    s[7]  = fmaf(x0, x3, s[7]);
    s[8]  = fmaf(x1, x1, s[8]);
    s[9]  = fmaf(x1, x2, s[9]);
    s[10] = fmaf(x1, x3, s[10]);
    s[11] = fmaf(x2, x3, s[11]);
    s[12] = fmaf(x2, x2, s[12]);
    s[13] = fmaf(x3, x3, s[13]);
}
// s layout: 0..3 sums; 4:00 5:01 6:02 7:03 8:11 9:12 10:13 11:23 12:22 13:33

// Pass 1: stats; evict_last policy pins x in L2 for pass2.
__global__ __launch_bounds__(256) void pass1_stats(const float* __restrict__ x) {
    const int f = blockIdx.x;   // 0..63
    const int bb = blockIdx.y;  // 0..31
    const size_t base = ((size_t)bb * 256 + f) * HW;
    const float4* __restrict__ p0 = (const float4*)(x + base);
    const float4* __restrict__ p1 = (const float4*)(x + base + (size_t)64  * HW);
    const float4* __restrict__ p2 = (const float4*)(x + base + (size_t)128 * HW);
    const float4* __restrict__ p3 = (const float4*)(x + base + (size_t)192 * HW);
    const unsigned long long pol = pol_evict_last();

    float s[NSTAT];
#pragma unroll
    for (int k = 0; k < NSTAT; k++) s[k] = 0.f;

#pragma unroll
    for (int half = 0; half < 2; half++) {
        const int i0 = threadIdx.x + half * 512;
        const int i1 = i0 + 256;
        float4 a0 = ldg_hint(p0 + i0, pol);
        float4 b0 = ldg_hint(p1 + i0, pol);
        float4 c0 = ldg_hint(p2 + i0, pol);
        float4 d0 = ldg_hint(p3 + i0, pol);
        float4 a1 = ldg_hint(p0 + i1, pol);
        float4 b1 = ldg_hint(p1 + i1, pol);
        float4 c1 = ldg_hint(p2 + i1, pol);
        float4 d1 = ldg_hint(p3 + i1, pol);
        acc4(a0.x, b0.x, c0.x, d0.x, s);
        acc4(a0.y, b0.y, c0.y, d0.y, s);
        acc4(a0.z, b0.z, c0.z, d0.z, s);
        acc4(a0.w, b0.w, c0.w, d0.w, s);
        acc4(a1.x, b1.x, c1.x, d1.x, s);
        acc4(a1.y, b1.y, c1.y, d1.y, s);
        acc4(a1.z, b1.z, c1.z, d1.z, s);
        acc4(a1.w, b1.w, c1.w, d1.w, s);
    }

#pragma unroll
    for (int k = 0; k < NSTAT; k++) {
#pragma unroll
        for (int off = 16; off; off >>= 1)
            s[k] += __shfl_down_sync(0xffffffffu, s[k], off);
    }

    __shared__ float sm[8][NSTAT];
    const int warp = threadIdx.x >> 5, lane = threadIdx.x & 31;
    if (lane == 0) {
#pragma unroll
        for (int k = 0; k < NSTAT; k++) sm[warp][k] = s[k];
    }
    __syncthreads();
    if (threadIdx.x < NSTAT) {
        float t = 0.f;
#pragma unroll
        for (int w = 0; w < 8; w++) t += sm[w][threadIdx.x];
        g_part[(f * BATCH + bb) * NSTAT + threadIdx.x] = t;
    }
}

__device__ __forceinline__ float4 mix4(float4 v0, float4 v1, float4 v2, float4 v3,
                                       float w0, float w1, float w2, float w3, float bb) {
    float4 o;
    o.x = fmaf(w0, v0.x, fmaf(w1, v1.x, fmaf(w2, v2.x, fmaf(w3, v3.x, bb))));
    o.y = fmaf(w0, v0.y, fmaf(w1, v1.y, fmaf(w2, v2.y, fmaf(w3, v3.y, bb))));
    o.z = fmaf(w0, v0.z, fmaf(w1, v1.z, fmaf(w2, v2.z, fmaf(w3, v3.z, bb))));
    o.w = fmaf(w0, v0.w, fmaf(w1, v1.w, fmaf(w2, v2.w, fmaf(w3, v3.w, bb))));
    return o;
}

// Pass 2: REVERSE block order; reads with evict_first policy (demote on hit),
// per-block redundant solve, fused whitening + affine: out = A*x + c.
__global__ __launch_bounds__(256) void pass2_apply(const float* __restrict__ x,
                                                   const float* __restrict__ weight,
                                                   const float* __restrict__ bias,
                                                   float* __restrict__ out) {
    const int rlin = (F_CH * BATCH - 1) - (blockIdx.y * F_CH + blockIdx.x);
    const int f  = rlin % F_CH;
    const int bb = rlin / F_CH;
    __shared__ float AC[20];

    if (threadIdx.x < 32) {
        const int lane = threadIdx.x;
        float s[NSTAT];
#pragma unroll
        for (int k = 0; k < NSTAT; k++) s[k] = g_part[(f * BATCH + lane) * NSTAT + k];
#pragma unroll
        for (int k = 0; k < NSTAT; k++) {
#pragma unroll
            for (int off = 16; off; off >>= 1)
                s[k] += __shfl_down_sync(0xffffffffu, s[k], off);
        }
        if (lane == 0) {
            const float invN = 1.0f / (float)(BATCH * HW);
            const float eps = 1e-5f;
            float m0 = s[0] * invN, m1 = s[1] * invN, m2 = s[2] * invN, m3 = s[3] * invN;
            float c00 = s[4]  * invN - m0 * m0 + eps;
            float c10 = s[5]  * invN - m0 * m1;
            float c20 = s[6]  * invN - m0 * m2;
            float c30 = s[7]  * invN - m0 * m3;
            float c11 = s[8]  * invN - m1 * m1 + eps;
            float c21 = s[9]  * invN - m1 * m2;
            float c31 = s[10] * invN - m1 * m3;
            float c32 = s[11] * invN - m2 * m3;
            float c22 = s[12] * invN - m2 * m2 + eps;
            float c33 = s[13] * invN - m3 * m3 + eps;

            float L00 = sqrtf(c00);
            float L10 = c10 / L00, L20 = c20 / L00, L30 = c30 / L00;
            float L11 = sqrtf(c11 - L10 * L10);
            float L21 = (c21 - L20 * L10) / L11;
            float L31 = (c31 - L30 * L10) / L11;
            float L22 = sqrtf(c22 - L20 * L20 - L21 * L21);
            float L32 = (c32 - L30 * L20 - L31 * L21) / L22;
            float L33 = sqrtf(c33 - L30 * L30 - L31 * L31 - L32 * L32);

            float i00 = 1.f / L00, i11 = 1.f / L11, i22 = 1.f / L22, i33 = 1.f / L33;
            float i10 = -(L10 * i00) * i11;
            float i20 = -(L20 * i00 + L21 * i10) * i22;
            float i21 = -(L21 * i11) * i22;
            float i30 = -(L30 * i00 + L31 * i10 + L32 * i20) * i33;
            float i31 = -(L31 * i11 + L32 * i21) * i33;
            float i32 = -(L32 * i22) * i33;

            float Linv[4][4] = {{i00, 0, 0, 0},
                                {i10, i11, 0, 0},
                                {i20, i21, i22, 0},
                                {i30, i31, i32, i33}};
            float m[4] = {m0, m1, m2, m3};
#pragma unroll
            for (int i = 0; i < 4; i++) {
                float A[4];
#pragma unroll
                for (int j = 0; j < 4; j++) {
                    float t = 0.f;
#pragma unroll
                    for (int k = 0; k < 4; k++)
                        if (k >= j) t = fmaf(weight[(i * 4 + k) * F_CH + f], Linv[k][j], t);
                    A[j] = t;
                    AC[i * 4 + j] = t;
                }
                AC[16 + i] = bias[i * F_CH + f]
                           - (A[0] * m[0] + A[1] * m[1] + A[2] * m[2] + A[3] * m[3]);
            }
        }
    }
    __syncthreads();

    float a00 = AC[0],  a01 = AC[1],  a02 = AC[2],  a03 = AC[3];
    float a10 = AC[4],  a11 = AC[5],  a12 = AC[6],  a13 = AC[7];
    float a20 = AC[8],  a21 = AC[9],  a22 = AC[10], a23 = AC[11];
    float a30 = AC[12], a31 = AC[13], a32 = AC[14], a33 = AC[15];
    float c0 = AC[16], c1 = AC[17], c2 = AC[18], c3 = AC[19];

    const size_t base = ((size_t)bb * 256 + f) * HW;
    const float4* __restrict__ p0 = (const float4*)(x + base);
    const float4* __restrict__ p1 = (const float4*)(x + base + (size_t)64  * HW);
    const float4* __restrict__ p2 = (const float4*)(x + base + (size_t)128 * HW);
    const float4* __restrict__ p3 = (const float4*)(x + base + (size_t)192 * HW);
    float4* __restrict__ q0 = (float4*)(out + base);
    float4* __restrict__ q1 = (float4*)(out + base + (size_t)64  * HW);
    float4* __restrict__ q2 = (float4*)(out + base + (size_t)128 * HW);
    float4* __restrict__ q3 = (float4*)(out + base + (size_t)192 * HW);
    const unsigned long long pol = pol_evict_first();

#pragma unroll
    for (int half = 0; half < 2; half++) {
        const int i0 = threadIdx.x + half * 512;
        const int i1 = i0 + 256;
        float4 v0 = ldg_hint(p0 + i0, pol);
        float4 v1 = ldg_hint(p1 + i0, pol);
        float4 v2 = ldg_hint(p2 + i0, pol);
        float4 v3 = ldg_hint(p3 + i0, pol);
        float4 w0 = ldg_hint(p0 + i1, pol);
        float4 w1 = ldg_hint(p1 + i1, pol);
        float4 w2 = ldg_hint(p2 + i1, pol);
        float4 w3 = ldg_hint(p3 + i1, pol);
        __stcs(q0 + i0, mix4(v0, v1, v2, v3, a00, a01, a02, a03, c0));
        __stcs(q1 + i0, mix4(v0, v1, v2, v3, a10, a11, a12, a13, c1));
        __stcs(q2 + i0, mix4(v0, v1, v2, v3, a20, a21, a22, a23, c2));
        __stcs(q3 + i0, mix4(v0, v1, v2, v3, a30, a31, a32, a33, c3));
        __stcs(q0 + i1, mix4(w0, w1, w2, w3, a00, a01, a02, a03, c0));
        __stcs(q1 + i1, mix4(w0, w1, w2, w3, a10, a11, a12, a13, c1));
        __stcs(q2 + i1, mix4(w0, w1, w2, w3, a20, a21, a22, a23, c2));
        __stcs(q3 + i1, mix4(w0, w1, w2, w3, a30, a31, a32, a33, c3));
    }
}

extern "C" void kernel_launch(void* const* d_in, const int* in_sizes, int n_in,
                              void* d_out, int out_size) {
    const float* x      = (const float*)d_in[0];
    const float* weight = (const float*)d_in[1];
    const float* bias   = (const float*)d_in[2];
    float* out = (float*)d_out;

    dim3 grid(F_CH, BATCH);
    pass1_stats<<<grid, 256>>>(x);
    pass2_apply<<<grid, 256>>>(x, weight, bias, out);
}